// round 3
// baseline (speedup 1.0000x reference)
#include <cuda_runtime.h>

// CrossAttention: out = softmax((x·Wq)(ctx·Wk)^T * DIM^-0.5) (ctx·Wv) + x
// Shapes: x[4,4096,512], ctx[4,4096,768], Wq[512,512], Wk/Wv[768,512]
// All dims are multiples of the tile sizes -> no bounds checks anywhere.

#define BATCH 4
#define SEQ_N 4096
#define SEQ_M 4096
#define DIM   512
#define CTXD  768

#define BM 128
#define BN 128
#define BK 16
#define TM 8
#define TN 8
#define PAD 4
#define NTHREADS 256   // (BM/TM)*(BN/TN)

// Scratch (allocation-free rule: __device__ globals).
__device__ float g_Q[(size_t)BATCH * SEQ_N * DIM];                 // 32 MB
__device__ float g_K[(size_t)BATCH * SEQ_M * DIM];                 // 32 MB
__device__ float g_V[(size_t)BATCH * SEQ_M * DIM];                 // 32 MB
__device__ float g_S[(size_t)BATCH * SEQ_N * SEQ_M];               // 256 MB

// Generic register-tiled fp32 GEMM.
//   C[b] = alpha * A[b] (Mrows x K, row-major) * B[b]  (+ residual)
//   B_KMAJOR=true : B stored [Ncols][K] row-major  -> computes A * B^T
//   B_KMAJOR=false: B stored [K][Ncols] row-major  -> computes A * B
// Row strides: A is K, B is K or Ncols, C/residual is Ncols.
template <bool B_KMAJOR, bool HAS_RES>
__global__ __launch_bounds__(NTHREADS, 2)
void gemm_kernel(const float* __restrict__ A, const float* __restrict__ B,
                 float* __restrict__ C, const float* __restrict__ R,
                 int Mrows, int Ncols, int K,
                 long strideA, long strideB, long strideC,
                 float alpha)
{
    __shared__ __align__(16) float As[BK][BM + PAD];
    __shared__ __align__(16) float Bs[BK][BN + PAD];

    const int bz = blockIdx.z;
    A += (long)bz * strideA;
    B += (long)bz * strideB;
    C += (long)bz * strideC;
    if (HAS_RES) R += (long)bz * strideC;

    const int bm  = blockIdx.y * BM;
    const int bn  = blockIdx.x * BN;
    const int tid = threadIdx.x;
    const int tx  = tid % (BN / TN);   // 0..15
    const int ty  = tid / (BN / TN);   // 0..15

    float acc[TM][TN];
#pragma unroll
    for (int i = 0; i < TM; i++)
#pragma unroll
        for (int j = 0; j < TN; j++) acc[i][j] = 0.0f;

    for (int kt = 0; kt < K; kt += BK) {
        // ---- load A tile (BM x BK), store transposed As[k][m]
        // BM*BK/4 = 512 float4s, 2 per thread
#pragma unroll
        for (int t = 0; t < 2; t++) {
            const int f   = tid + t * NTHREADS;
            const int row = f >> 2;            // f / (BK/4)
            const int kc  = (f & 3) << 2;
            const float4 v = *reinterpret_cast<const float4*>(
                A + (long)(bm + row) * K + kt + kc);
            As[kc + 0][row] = v.x;
            As[kc + 1][row] = v.y;
            As[kc + 2][row] = v.z;
            As[kc + 3][row] = v.w;
        }
        // ---- load B tile into Bs[k][n]
        if (B_KMAJOR) {
#pragma unroll
            for (int t = 0; t < 2; t++) {
                const int f   = tid + t * NTHREADS;
                const int row = f >> 2;        // output-column index within tile
                const int kc  = (f & 3) << 2;
                const float4 v = *reinterpret_cast<const float4*>(
                    B + (long)(bn + row) * K + kt + kc);
                Bs[kc + 0][row] = v.x;
                Bs[kc + 1][row] = v.y;
                Bs[kc + 2][row] = v.z;
                Bs[kc + 3][row] = v.w;
            }
        } else {
#pragma unroll
            for (int t = 0; t < 2; t++) {
                const int f  = tid + t * NTHREADS;
                const int kr = f >> 5;         // f / (BN/4)
                const int nc = (f & 31) << 2;
                const float4 v = *reinterpret_cast<const float4*>(
                    B + (long)(kt + kr) * Ncols + bn + nc);
                *reinterpret_cast<float4*>(&Bs[kr][nc]) = v;
            }
        }
        __syncthreads();

#pragma unroll
        for (int k = 0; k < BK; k++) {
            float ra[TM], rb[TN];
#pragma unroll
            for (int i = 0; i < TM; i++) ra[i] = As[k][ty * TM + i];
#pragma unroll
            for (int j = 0; j < TN; j++) rb[j] = Bs[k][tx * TN + j];
#pragma unroll
            for (int i = 0; i < TM; i++)
#pragma unroll
                for (int j = 0; j < TN; j++)
                    acc[i][j] += ra[i] * rb[j];
        }
        __syncthreads();
    }

    // ---- epilogue: scale (+ residual), vectorized stores
#pragma unroll
    for (int i = 0; i < TM; i++) {
        const long crow = bm + ty * TM + i;
        float* cp = C + crow * Ncols + bn + tx * TN;
        const float* rp = HAS_RES ? (R + crow * Ncols + bn + tx * TN) : nullptr;
#pragma unroll
        for (int j = 0; j < TN; j += 4) {
            float4 v;
            v.x = acc[i][j + 0] * alpha;
            v.y = acc[i][j + 1] * alpha;
            v.z = acc[i][j + 2] * alpha;
            v.w = acc[i][j + 3] * alpha;
            if (HAS_RES) {
                const float4 r = *reinterpret_cast<const float4*>(rp + j);
                v.x += r.x; v.y += r.y; v.z += r.z; v.w += r.w;
            }
            *reinterpret_cast<float4*>(cp + j) = v;
        }
    }
}

// In-place row softmax over SEQ_M=4096 columns. One block per row, 256 threads,
// 16 elements per thread held in registers across both passes.
__global__ __launch_bounds__(256)
void softmax_kernel(float* __restrict__ S)
{
    constexpr int VPT = SEQ_M / 256;   // 16
    float* row = S + (long)blockIdx.x * SEQ_M;
    const int tid = threadIdx.x;

    float v[VPT];
    float lmax = -1e30f;
#pragma unroll
    for (int t = 0; t < VPT; t++) {
        v[t] = row[tid + t * 256];
        lmax = fmaxf(lmax, v[t]);
    }
#pragma unroll
    for (int o = 16; o > 0; o >>= 1)
        lmax = fmaxf(lmax, __shfl_xor_sync(0xFFFFFFFFu, lmax, o));

    __shared__ float redmax[8];
    __shared__ float redsum[8];
    if ((tid & 31) == 0) redmax[tid >> 5] = lmax;
    __syncthreads();
    float bmax = redmax[0];
#pragma unroll
    for (int w = 1; w < 8; w++) bmax = fmaxf(bmax, redmax[w]);

    float lsum = 0.0f;
#pragma unroll
    for (int t = 0; t < VPT; t++) {
        v[t] = __expf(v[t] - bmax);
        lsum += v[t];
    }
#pragma unroll
    for (int o = 16; o > 0; o >>= 1)
        lsum += __shfl_xor_sync(0xFFFFFFFFu, lsum, o);
    if ((tid & 31) == 0) redsum[tid >> 5] = lsum;
    __syncthreads();
    float bsum = 0.0f;
#pragma unroll
    for (int w = 0; w < 8; w++) bsum += redsum[w];

    const float inv = 1.0f / bsum;
#pragma unroll
    for (int t = 0; t < VPT; t++)
        row[tid + t * 256] = v[t] * inv;
}

extern "C" void kernel_launch(void* const* d_in, const int* in_sizes, int n_in,
                              void* d_out, int out_size)
{
    const float* x   = (const float*)d_in[0];   // [4,4096,512]
    const float* ctx = (const float*)d_in[1];   // [4,4096,768]
    const float* Wq  = (const float*)d_in[2];   // [512,512]
    const float* Wk  = (const float*)d_in[3];   // [768,512]
    const float* Wv  = (const float*)d_in[4];   // [768,512]
    float* out = (float*)d_out;                 // [4,4096,512]

    float *Q, *K, *V, *S;
    cudaGetSymbolAddress((void**)&Q, g_Q);
    cudaGetSymbolAddress((void**)&K, g_K);
    cudaGetSymbolAddress((void**)&V, g_V);
    cudaGetSymbolAddress((void**)&S, g_S);

    const float scale = 0.044194173824159216f;  // 512^-0.5
    const dim3 thr(NTHREADS);

    // Projections (batch folded into rows: 16384 x 512)
    gemm_kernel<false, false><<<dim3(DIM / BN, (BATCH * SEQ_N) / BM, 1), thr>>>(
        x, Wq, Q, nullptr, BATCH * SEQ_N, DIM, DIM, 0, 0, 0, 1.0f);
    gemm_kernel<false, false><<<dim3(DIM / BN, (BATCH * SEQ_M) / BM, 1), thr>>>(
        ctx, Wk, K, nullptr, BATCH * SEQ_M, DIM, CTXD, 0, 0, 0, 1.0f);
    gemm_kernel<false, false><<<dim3(DIM / BN, (BATCH * SEQ_M) / BM, 1), thr>>>(
        ctx, Wv, V, nullptr, BATCH * SEQ_M, DIM, CTXD, 0, 0, 0, 1.0f);

    // S = scale * Q K^T (batched, NT)
    gemm_kernel<true, false><<<dim3(SEQ_M / BN, SEQ_N / BM, BATCH), thr>>>(
        Q, K, S, nullptr, SEQ_N, SEQ_M, DIM,
        (long)SEQ_N * DIM, (long)SEQ_M * DIM, (long)SEQ_N * SEQ_M, scale);

    // softmax rows (in place)
    softmax_kernel<<<BATCH * SEQ_N, 256>>>(S);

    // out = P V + x (batched, NN, residual fused)
    gemm_kernel<false, true><<<dim3(DIM / BN, SEQ_N / BM, BATCH), thr>>>(
        S, V, out, x, SEQ_N, DIM, SEQ_M,
        (long)SEQ_N * SEQ_M, (long)SEQ_M * DIM, (long)SEQ_N * DIM, 1.0f);
}

// round 5
// speedup vs baseline: 6.6634x; 6.6634x over previous
#include <cuda_runtime.h>
#include <cuda_bf16.h>
#include <cstdint>

// CrossAttention, bf16 mma.sync (compute_100-safe: ldmatrix + mma + cp.async):
//   out = softmax((x Wq)(ctx Wk)^T * DIM^-0.5) (ctx Wv) + x
// x[4,4096,512] ctx[4,4096,768] Wq[512,512] Wk/Wv[768,512]

#define BATCH 4
#define SEQ   4096
#define DIM   512
#define CTXD  768

typedef __nv_bfloat16 bf16;

// ---------------- scratch (__device__ globals; allocation-free rule) --------
__device__ bf16  g_Xb [(size_t)BATCH * SEQ * DIM];
__device__ bf16  g_Cb [(size_t)BATCH * SEQ * CTXD];
__device__ bf16  g_WqT[(size_t)DIM * DIM];
__device__ bf16  g_WkT[(size_t)DIM * CTXD];
__device__ bf16  g_WvT[(size_t)DIM * CTXD];
__device__ bf16  g_Qb [(size_t)BATCH * SEQ * DIM];
__device__ bf16  g_Kb [(size_t)BATCH * SEQ * DIM];
__device__ bf16  g_Vb [(size_t)BATCH * SEQ * DIM];
__device__ bf16  g_VT [(size_t)BATCH * DIM * SEQ];
__device__ float g_S  [(size_t)BATCH * SEQ * SEQ];
__device__ bf16  g_P  [(size_t)BATCH * SEQ * SEQ];

// ---------------- PTX helpers (all sm_80/90-era, compute_100-clean) ---------
__device__ __forceinline__ uint32_t smem_u32(const void* p) {
    uint32_t a;
    asm("{ .reg .u64 t; cvta.to.shared.u64 t, %1; cvt.u32.u64 %0, t; }"
        : "=r"(a) : "l"(p));
    return a;
}
#define CP_ASYNC16(dst, src) \
    asm volatile("cp.async.cg.shared.global [%0], [%1], 16;" :: "r"(dst), "l"(src))
#define CP_COMMIT() asm volatile("cp.async.commit_group;" ::: "memory")
#define CP_WAIT(n)  asm volatile("cp.async.wait_group %0;" :: "n"(n) : "memory")

#define LDSM4(r0, r1, r2, r3, addr) \
    asm volatile("ldmatrix.sync.aligned.m8n8.x4.shared.b16 {%0,%1,%2,%3}, [%4];" \
        : "=r"(r0), "=r"(r1), "=r"(r2), "=r"(r3) : "r"(addr))

#define MMA16816(d, a, b) \
    asm volatile("mma.sync.aligned.m16n8k16.row.col.f32.bf16.bf16.f32 " \
        "{%0,%1,%2,%3}, {%4,%5,%6,%7}, {%8,%9}, {%0,%1,%2,%3};" \
        : "+f"((d)[0]), "+f"((d)[1]), "+f"((d)[2]), "+f"((d)[3]) \
        : "r"((a)[0]), "r"((a)[1]), "r"((a)[2]), "r"((a)[3]), \
          "r"((b)[0]), "r"((b)[1]))

__device__ __forceinline__ uint32_t pk2(float lo, float hi) {
    __nv_bfloat162 h = __floats2bfloat162_rn(lo, hi);
    return *reinterpret_cast<uint32_t*>(&h);
}

// ---------------- bf16 mma GEMM: D = A(M,K) * B(N,K)^T ----------------------
// CTA tile 128x128, BK=64 (128B rows, SW128 swizzle), 3-stage cp.async.
// 8 warps: 2(M) x 4(N); warp tile 64x32; mma m16n8k16.
// MODE: 0 = bf16 out, 1 = f32 out * alpha, 2 = f32 out + residual.

#define STAGES 3
#define STAGE_BYTES 32768           // A 16KB + B 16KB
#define GEMM_SMEM (STAGES * STAGE_BYTES + 128)

// load one 128x64 bf16 tile (g, row stride ld elems) into swizzled smem stage
__device__ __forceinline__ void tile_async(const bf16* g, int ld, uint32_t stg, int tid) {
#pragma unroll
    for (int t = 0; t < 4; t++) {
        const int f   = tid + t * 256;
        const int row = f >> 3;
        const int seg = f & 7;
        const uint32_t dst = stg + row * 128 + ((seg ^ (row & 7)) << 4);
        CP_ASYNC16(dst, (const char*)g + (long)row * ld * 2 + seg * 16);
    }
}

template <int MODE>
__global__ __launch_bounds__(256)
void gemm_mma(const bf16* __restrict__ A, const bf16* __restrict__ B,
              void* __restrict__ Cv, const float* __restrict__ R,
              int Ncols, int Kd, long sA, long sB, long sC, float alpha)
{
    extern __shared__ char smraw[];
    const uint32_t smbase = (smem_u32(smraw) + 127u) & ~127u;

    const int tid  = threadIdx.x;
    const int lane = tid & 31;
    const int wid  = tid >> 5;
    const int wm   = wid >> 2;                 // 0..1
    const int wn   = wid & 3;                  // 0..3
    const int bz   = blockIdx.z;
    const long bm  = (long)blockIdx.y * 128;
    const long bn  = (long)blockIdx.x * 128;

    A += bz * sA + bm * Kd;
    B += bz * sB + bn * Kd;

    // ldmatrix per-lane geometry (SW128: seg' = seg ^ (row & 7))
    const int g  = lane >> 3, lr = lane & 7;
    const int arow0 = wm * 64 + (g & 1) * 8 + lr;
    const int aseg0 = g >> 1;
    const int axor  = arow0 & 7;
    const int brow0 = wn * 32 + (g >> 1) * 8 + lr;
    const int bseg0 = g & 1;
    const int bxor  = brow0 & 7;

    float acc[4][4][4];
#pragma unroll
    for (int i = 0; i < 4; i++)
#pragma unroll
        for (int j = 0; j < 4; j++)
#pragma unroll
            for (int q = 0; q < 4; q++) acc[i][j][q] = 0.0f;

    const int NC = Kd >> 6;

    // prologue: stages 0,1
#pragma unroll
    for (int c = 0; c < 2; c++) {
        const uint32_t stg = smbase + c * STAGE_BYTES;
        tile_async(A + c * 64, Kd, stg, tid);
        tile_async(B + c * 64, Kd, stg + 16384, tid);
        CP_COMMIT();
    }

    for (int c = 0; c < NC; c++) {
        if (c == NC - 1) { CP_WAIT(0); } else { CP_WAIT(1); }
        __syncthreads();

        if (c + 2 < NC) {
            const uint32_t stg = smbase + ((c + 2) % STAGES) * STAGE_BYTES;
            tile_async(A + (c + 2) * 64, Kd, stg, tid);
            tile_async(B + (c + 2) * 64, Kd, stg + 16384, tid);
            CP_COMMIT();
        }

        const uint32_t sa = smbase + (c % STAGES) * STAGE_BYTES;
        const uint32_t sb = sa + 16384;
#pragma unroll
        for (int ks = 0; ks < 4; ks++) {
            uint32_t af[4][4];
#pragma unroll
            for (int i = 0; i < 4; i++)
                LDSM4(af[i][0], af[i][1], af[i][2], af[i][3],
                      sa + (arow0 + i * 16) * 128 + ((((ks << 1) + aseg0) ^ axor) << 4));
            uint32_t bfr[4][2];
#pragma unroll
            for (int jp = 0; jp < 2; jp++) {
                uint32_t r0, r1, r2, r3;
                LDSM4(r0, r1, r2, r3,
                      sb + (brow0 + jp * 16) * 128 + ((((ks << 1) + bseg0) ^ bxor) << 4));
                bfr[2 * jp][0] = r0; bfr[2 * jp][1] = r1;
                bfr[2 * jp + 1][0] = r2; bfr[2 * jp + 1][1] = r3;
            }
#pragma unroll
            for (int i = 0; i < 4; i++)
#pragma unroll
                for (int j = 0; j < 4; j++)
                    MMA16816(acc[i][j], af[i], bfr[j]);
        }
    }

    // ---------------- epilogue ----------------
    const int r  = lane >> 2;
    const int c2 = (lane & 3) * 2;
    const long rowBase = bm + wm * 64;
    const int  colBase = bn + wn * 32;

#pragma unroll
    for (int i = 0; i < 4; i++) {
#pragma unroll
        for (int j = 0; j < 4; j++) {
            const long row0 = rowBase + i * 16 + r;
            const int  col  = colBase + j * 8 + c2;
            const long o0 = (row0)     * (long)Ncols + col + bz * sC;
            const long o1 = (row0 + 8) * (long)Ncols + col + bz * sC;
            if (MODE == 0) {
                *(uint32_t*)((bf16*)Cv + o0) = pk2(acc[i][j][0], acc[i][j][1]);
                *(uint32_t*)((bf16*)Cv + o1) = pk2(acc[i][j][2], acc[i][j][3]);
            } else if (MODE == 1) {
                *(float2*)((float*)Cv + o0) =
                    make_float2(acc[i][j][0] * alpha, acc[i][j][1] * alpha);
                *(float2*)((float*)Cv + o1) =
                    make_float2(acc[i][j][2] * alpha, acc[i][j][3] * alpha);
            } else {
                const float2 r0 = *(const float2*)(R + o0);
                const float2 r1 = *(const float2*)(R + o1);
                *(float2*)((float*)Cv + o0) =
                    make_float2(acc[i][j][0] + r0.x, acc[i][j][1] + r0.y);
                *(float2*)((float*)Cv + o1) =
                    make_float2(acc[i][j][2] + r1.x, acc[i][j][3] + r1.y);
            }
        }
    }
}

// ---------------- helper kernels -------------------------------------------
__global__ __launch_bounds__(256)
void cvt_bf16(const float* __restrict__ in, bf16* __restrict__ out) {
    const long i = (long)blockIdx.x * 256 + threadIdx.x;
    const float4* p = (const float4*)in + i * 2;
    const float4 a = p[0], b = p[1];
    ((uint4*)out)[i] = make_uint4(pk2(a.x, a.y), pk2(a.z, a.w),
                                  pk2(b.x, b.y), pk2(b.z, b.w));
}

__global__ __launch_bounds__(256)
void wtransb(const float* __restrict__ W, bf16* __restrict__ WT, int Kin, int Nout) {
    __shared__ float t[32][33];
    const int n0 = blockIdx.x * 32, k0 = blockIdx.y * 32;
    const int tx = threadIdx.x & 31, ty = threadIdx.x >> 5;
#pragma unroll
    for (int i = 0; i < 4; i++)
        t[ty + 8 * i][tx] = W[(long)(k0 + ty + 8 * i) * Nout + n0 + tx];
    __syncthreads();
#pragma unroll
    for (int i = 0; i < 4; i++)
        WT[(long)(n0 + ty + 8 * i) * Kin + k0 + tx] = __float2bfloat16(t[tx][ty + 8 * i]);
}

__global__ __launch_bounds__(256)
void vtransb(const bf16* __restrict__ V, bf16* __restrict__ VT) {
    __shared__ bf16 t[32][33];
    const long boff = (long)blockIdx.z * SEQ * DIM;
    const int d0 = blockIdx.x * 32, m0 = blockIdx.y * 32;
    const int tx = threadIdx.x & 31, ty = threadIdx.x >> 5;
#pragma unroll
    for (int i = 0; i < 4; i++)
        t[ty + 8 * i][tx] = V[boff + (long)(m0 + ty + 8 * i) * DIM + d0 + tx];
    __syncthreads();
#pragma unroll
    for (int i = 0; i < 4; i++)
        VT[boff + (long)(d0 + ty + 8 * i) * SEQ + m0 + tx] = t[tx][ty + 8 * i];
}

__global__ __launch_bounds__(256)
void softmax_bf16(const float* __restrict__ S, bf16* __restrict__ P) {
    const long row = blockIdx.x;
    const int tid = threadIdx.x;
    const float4* rp = (const float4*)(S + row * SEQ) + tid * 4;
    float v[16];
#pragma unroll
    for (int q = 0; q < 4; q++) {
        const float4 a = rp[q];
        v[4 * q] = a.x; v[4 * q + 1] = a.y; v[4 * q + 2] = a.z; v[4 * q + 3] = a.w;
    }
    float lmax = -1e30f;
#pragma unroll
    for (int t = 0; t < 16; t++) lmax = fmaxf(lmax, v[t]);
#pragma unroll
    for (int o = 16; o > 0; o >>= 1)
        lmax = fmaxf(lmax, __shfl_xor_sync(0xFFFFFFFFu, lmax, o));
    __shared__ float rmax[8], rsum[8];
    if ((tid & 31) == 0) rmax[tid >> 5] = lmax;
    __syncthreads();
    float bmax = rmax[0];
#pragma unroll
    for (int w = 1; w < 8; w++) bmax = fmaxf(bmax, rmax[w]);
    float lsum = 0.0f;
#pragma unroll
    for (int t = 0; t < 16; t++) { v[t] = __expf(v[t] - bmax); lsum += v[t]; }
#pragma unroll
    for (int o = 16; o > 0; o >>= 1)
        lsum += __shfl_xor_sync(0xFFFFFFFFu, lsum, o);
    if ((tid & 31) == 0) rsum[tid >> 5] = lsum;
    __syncthreads();
    float bsum = 0.0f;
#pragma unroll
    for (int w = 0; w < 8; w++) bsum += rsum[w];
    const float inv = 1.0f / bsum;
    uint4* dst = (uint4*)(P + row * SEQ + tid * 16);
#pragma unroll
    for (int q = 0; q < 2; q++) {
        uint4 o;
        o.x = pk2(v[8 * q + 0] * inv, v[8 * q + 1] * inv);
        o.y = pk2(v[8 * q + 2] * inv, v[8 * q + 3] * inv);
        o.z = pk2(v[8 * q + 4] * inv, v[8 * q + 5] * inv);
        o.w = pk2(v[8 * q + 6] * inv, v[8 * q + 7] * inv);
        dst[q] = o;
    }
}

// ---------------- launcher ---------------------------------------------------
extern "C" void kernel_launch(void* const* d_in, const int* in_sizes, int n_in,
                              void* d_out, int out_size)
{
    const float* x   = (const float*)d_in[0];
    const float* ctx = (const float*)d_in[1];
    const float* Wq  = (const float*)d_in[2];
    const float* Wk  = (const float*)d_in[3];
    const float* Wv  = (const float*)d_in[4];
    float* out = (float*)d_out;

    bf16 *Xb, *Cb, *WqT, *WkT, *WvT, *Qb, *Kb, *Vb, *VT, *P;
    float* S;
    cudaGetSymbolAddress((void**)&Xb,  g_Xb);
    cudaGetSymbolAddress((void**)&Cb,  g_Cb);
    cudaGetSymbolAddress((void**)&WqT, g_WqT);
    cudaGetSymbolAddress((void**)&WkT, g_WkT);
    cudaGetSymbolAddress((void**)&WvT, g_WvT);
    cudaGetSymbolAddress((void**)&Qb,  g_Qb);
    cudaGetSymbolAddress((void**)&Kb,  g_Kb);
    cudaGetSymbolAddress((void**)&Vb,  g_Vb);
    cudaGetSymbolAddress((void**)&VT,  g_VT);
    cudaGetSymbolAddress((void**)&S,   g_S);
    cudaGetSymbolAddress((void**)&P,   g_P);

    cudaFuncSetAttribute(gemm_mma<0>, cudaFuncAttributeMaxDynamicSharedMemorySize, GEMM_SMEM);
    cudaFuncSetAttribute(gemm_mma<1>, cudaFuncAttributeMaxDynamicSharedMemorySize, GEMM_SMEM);
    cudaFuncSetAttribute(gemm_mma<2>, cudaFuncAttributeMaxDynamicSharedMemorySize, GEMM_SMEM);

    const float scale = 0.044194173824159216f;  // 512^-0.5

    cvt_bf16<<<(BATCH * SEQ * DIM)  / (256 * 8), 256>>>(x,   Xb);
    cvt_bf16<<<(BATCH * SEQ * CTXD) / (256 * 8), 256>>>(ctx, Cb);

    wtransb<<<dim3(DIM / 32, DIM  / 32), 256>>>(Wq, WqT, DIM,  DIM);
    wtransb<<<dim3(DIM / 32, CTXD / 32), 256>>>(Wk, WkT, CTXD, DIM);
    wtransb<<<dim3(DIM / 32, CTXD / 32), 256>>>(Wv, WvT, CTXD, DIM);

    // projections (batch folded: 16384 rows)
    gemm_mma<0><<<dim3(DIM / 128, (BATCH * SEQ) / 128, 1), 256, GEMM_SMEM>>>(
        Xb, WqT, Qb, nullptr, DIM, DIM, 0, 0, 0, 1.0f);
    gemm_mma<0><<<dim3(DIM / 128, (BATCH * SEQ) / 128, 1), 256, GEMM_SMEM>>>(
        Cb, WkT, Kb, nullptr, DIM, CTXD, 0, 0, 0, 1.0f);
    gemm_mma<0><<<dim3(DIM / 128, (BATCH * SEQ) / 128, 1), 256, GEMM_SMEM>>>(
        Cb, WvT, Vb, nullptr, DIM, CTXD, 0, 0, 0, 1.0f);

    vtransb<<<dim3(DIM / 32, SEQ / 32, BATCH), 256>>>(Vb, VT);

    // S = scale * Q K^T
    gemm_mma<1><<<dim3(SEQ / 128, SEQ / 128, BATCH), 256, GEMM_SMEM>>>(
        Qb, Kb, S, nullptr, SEQ, DIM,
        (long)SEQ * DIM, (long)SEQ * DIM, (long)SEQ * SEQ, scale);

    softmax_bf16<<<BATCH * SEQ, 256>>>(S, P);

    // out = P V + x
    gemm_mma<2><<<dim3(DIM / 128, SEQ / 128, BATCH), 256, GEMM_SMEM>>>(
        P, VT, out, x, DIM, SEQ,
        (long)SEQ * SEQ, (long)DIM * SEQ, (long)SEQ * DIM, 1.0f);
}